// round 6
// baseline (speedup 1.0000x reference)
#include <cuda_runtime.h>

// Problem constants: B=8, L=96, H=8, E=64, EH=128. Rows = B*H = 64.
#define NT 256

typedef unsigned long long ull;

__device__ __forceinline__ ull pack2(float lo, float hi) {
    ull r; asm("mov.b64 %0, {%1, %2};" : "=l"(r) : "f"(lo), "f"(hi)); return r;
}
__device__ __forceinline__ void unpack2(ull v, float& lo, float& hi) {
    asm("mov.b64 {%0, %1}, %2;" : "=f"(lo), "=f"(hi) : "l"(v));
}
__device__ __forceinline__ void ffma2(ull& acc, ull a, ull b) {
    asm("fma.rn.f32x2 %0, %1, %2, %0;" : "+l"(acc) : "l"(a), "l"(b));
}

// GEMM1: sHT[c*64+r] = tanh(b1[c] + sum_k inT[k*64+r] * W1[k*128+c]); r<64, c<128, k<64
// Thread tile: 4 rows x 8 cols. 16 rtiles x 16 ctiles = 256 threads.
__device__ __noinline__ void gemm1(const float* __restrict__ inT,
                                   const float* __restrict__ sW1,
                                   const float* __restrict__ sb1,
                                   float* __restrict__ sHT, int t)
{
    const int r0 = (t & 15) * 4;
    const int c0 = (t >> 4) * 8;
    ull acc[4][4];
    {
        ull i0 = pack2(sb1[c0 + 0], sb1[c0 + 1]);
        ull i1 = pack2(sb1[c0 + 2], sb1[c0 + 3]);
        ull i2 = pack2(sb1[c0 + 4], sb1[c0 + 5]);
        ull i3 = pack2(sb1[c0 + 6], sb1[c0 + 7]);
#pragma unroll
        for (int r = 0; r < 4; r++) { acc[r][0] = i0; acc[r][1] = i1; acc[r][2] = i2; acc[r][3] = i3; }
    }
#pragma unroll 8
    for (int k = 0; k < 64; k++) {
        float4 a = *(const float4*)(inT + k * 64 + r0);
        ull ap0 = pack2(a.x, a.x), ap1 = pack2(a.y, a.y), ap2 = pack2(a.z, a.z), ap3 = pack2(a.w, a.w);
        ulonglong2 wa = *(const ulonglong2*)(sW1 + k * 128 + c0);
        ulonglong2 wb = *(const ulonglong2*)(sW1 + k * 128 + c0 + 4);
        ffma2(acc[0][0], ap0, wa.x); ffma2(acc[0][1], ap0, wa.y); ffma2(acc[0][2], ap0, wb.x); ffma2(acc[0][3], ap0, wb.y);
        ffma2(acc[1][0], ap1, wa.x); ffma2(acc[1][1], ap1, wa.y); ffma2(acc[1][2], ap1, wb.x); ffma2(acc[1][3], ap1, wb.y);
        ffma2(acc[2][0], ap2, wa.x); ffma2(acc[2][1], ap2, wa.y); ffma2(acc[2][2], ap2, wb.x); ffma2(acc[2][3], ap2, wb.y);
        ffma2(acc[3][0], ap3, wa.x); ffma2(acc[3][1], ap3, wa.y); ffma2(acc[3][2], ap3, wb.x); ffma2(acc[3][3], ap3, wb.y);
    }
#pragma unroll
    for (int j = 0; j < 4; j++) {
        float l0, h0, l1, h1, l2, h2, l3, h3;
        unpack2(acc[0][j], l0, h0);
        unpack2(acc[1][j], l1, h1);
        unpack2(acc[2][j], l2, h2);
        unpack2(acc[3][j], l3, h3);
        float4 e;
        e.x = tanhf(l0); e.y = tanhf(l1); e.z = tanhf(l2); e.w = tanhf(l3);
        *(float4*)(sHT + (c0 + 2 * j) * 64 + r0) = e;
        e.x = tanhf(h0); e.y = tanhf(h1); e.z = tanhf(h2); e.w = tanhf(h3);
        *(float4*)(sHT + (c0 + 2 * j + 1) * 64 + r0) = e;
    }
}

// GEMM2: outT[e*64+r] = b2[e] + sum_c sHT[c*64+r] * W2[c*64+e]; r<64, e<64, c<128
// Thread tile: 4 rows x 4 cols. Output written transposed ([e][r]) for the next GEMM1.
__device__ __noinline__ void gemm2(float* __restrict__ outT,
                                   const float* __restrict__ sHT,
                                   const float* __restrict__ sW2,
                                   const float* __restrict__ sb2, int t)
{
    const int r0 = (t & 15) * 4;
    const int e0 = (t >> 4) * 4;
    ull acc[4][2];
    {
        ull i0 = pack2(sb2[e0 + 0], sb2[e0 + 1]);
        ull i1 = pack2(sb2[e0 + 2], sb2[e0 + 3]);
#pragma unroll
        for (int r = 0; r < 4; r++) { acc[r][0] = i0; acc[r][1] = i1; }
    }
#pragma unroll 8
    for (int c = 0; c < 128; c++) {
        float4 h = *(const float4*)(sHT + c * 64 + r0);
        ull h0 = pack2(h.x, h.x), h1 = pack2(h.y, h.y), h2 = pack2(h.z, h.z), h3 = pack2(h.w, h.w);
        ulonglong2 w = *(const ulonglong2*)(sW2 + c * 64 + e0);
        ffma2(acc[0][0], h0, w.x); ffma2(acc[0][1], h0, w.y);
        ffma2(acc[1][0], h1, w.x); ffma2(acc[1][1], h1, w.y);
        ffma2(acc[2][0], h2, w.x); ffma2(acc[2][1], h2, w.y);
        ffma2(acc[3][0], h3, w.x); ffma2(acc[3][1], h3, w.y);
    }
#pragma unroll
    for (int j = 0; j < 2; j++) {
        float l0, h0, l1, h1, l2, h2, l3, h3;
        unpack2(acc[0][j], l0, h0);
        unpack2(acc[1][j], l1, h1);
        unpack2(acc[2][j], l2, h2);
        unpack2(acc[3][j], l3, h3);
        *(float4*)(outT + (e0 + 2 * j) * 64 + r0)     = make_float4(l0, l1, l2, l3);
        *(float4*)(outT + (e0 + 2 * j + 1) * 64 + r0) = make_float4(h0, h1, h2, h3);
    }
}

__global__ void __launch_bounds__(NT, 1) ode_chain_kernel(
    const float* __restrict__ gx, const float* __restrict__ gts,
    const float* __restrict__ gW1, const float* __restrict__ gb1,
    const float* __restrict__ gW2, const float* __restrict__ gb2,
    float2* __restrict__ out)
{
    extern __shared__ float sm[];
    float* sW1 = sm;             // 8192  [k*128+c]
    float* sW2 = sW1 + 8192;     // 8192  [c*64+e]
    float* sHT = sW2 + 8192;     // 8192  [c*64+r]
    float* sY  = sHT + 8192;     // 4096  [e*64+r]
    float* sK1 = sY  + 4096;
    float* sK2 = sK1 + 4096;
    float* sK3 = sK2 + 4096;
    float* sAR = sK3 + 4096;
    float* sb1 = sAR + 4096;     // 128
    float* sb2 = sb1 + 128;      // 64
    float* sTs = sb2 + 64;       // 96

    const int t = threadIdx.x;
    const int blk = blockIdx.x;
    const int p = blk >> 1;
    const bool fw = (blk & 1) == 0;          // longest-first pairing: (fwd p, bwd 95-p)
    const int idx = fw ? p : (95 - p);

    // Cooperative loads of weights / biases / timeslots
    for (int q = t; q < 8192; q += NT) { sW1[q] = gW1[q]; sW2[q] = gW2[q]; }
    if (t < 128) sb1[t] = gb1[t];
    if (t < 64)  sb2[t] = gb2[t];
    if (t < 96)  sTs[t] = gts[t];

    // Initial state S0 (transposed): sY[e*64+r] = x[b, idx, h, e], r = b*8 + h
    for (int q = t; q < 4096; q += NT) {
        int r = q >> 6, e = q & 63;
        int b = r >> 3, h = r & 7;
        sY[e * 64 + r] = gx[(((b * 96 + idx) * 8 + h) << 6) + e];
    }

    // Per-thread cached x0 slice for emission: thread owns row er, e-range eq*16..+15
    const int er = t >> 2, eq = t & 3;
    const int eb = er >> 3, eh = er & 7;
    float x0v[16];
    {
        const float* xp = gx + (((eb * 96 + idx) * 8 + eh) << 6) + eq * 16;
#pragma unroll
        for (int i = 0; i < 16; i += 4) {
            float4 v = *(const float4*)(xp + i);
            x0v[i] = v.x; x0v[i + 1] = v.y; x0v[i + 2] = v.z; x0v[i + 3] = v.w;
        }
    }
    __syncthreads();

#define EMIT(J)                                                                        \
    {                                                                                  \
        size_t ob = ((((size_t)eb * 96 + idx) * 96 + (J)) * 8 + eh) * 64 + eq * 16;    \
        _Pragma("unroll")                                                              \
        for (int i = 0; i < 16; i += 2) {                                              \
            int e = eq * 16 + i;                                                       \
            float y0 = sY[e * 64 + er];                                                \
            float y1 = sY[(e + 1) * 64 + er];                                          \
            *(float4*)(out + ob + i) = make_float4(x0v[i], y0, x0v[i + 1], y1);        \
        }                                                                              \
    }

    const int ew0 = t * 16;
#define RK4STEP(DT)                                                                    \
    {                                                                                  \
        const float dt_ = (DT);                                                        \
        /* k1 = f(y) */                                                                \
        gemm1(sY, sW1, sb1, sHT, t); __syncthreads();                                  \
        gemm2(sK1, sHT, sW2, sb2, t); __syncthreads();                                 \
        { /* arg = y + (dt/3) k1 */                                                    \
            float c = dt_ * (1.0f / 3.0f);                                             \
            _Pragma("unroll")                                                          \
            for (int i = 0; i < 16; i += 4) {                                          \
                int o = ew0 + i;                                                       \
                float4 y = *(float4*)(sY + o), k = *(float4*)(sK1 + o);                \
                *(float4*)(sAR + o) = make_float4(y.x + c * k.x, y.y + c * k.y,        \
                                                  y.z + c * k.z, y.w + c * k.w);       \
            }                                                                          \
        }                                                                              \
        __syncthreads();                                                               \
        /* k2 = f(arg) */                                                              \
        gemm1(sAR, sW1, sb1, sHT, t); __syncthreads();                                 \
        gemm2(sK2, sHT, sW2, sb2, t); __syncthreads();                                 \
        { /* arg = y + dt*(k2 - k1/3) */                                               \
            const float th = 1.0f / 3.0f;                                              \
            _Pragma("unroll")                                                          \
            for (int i = 0; i < 16; i += 4) {                                          \
                int o = ew0 + i;                                                       \
                float4 y = *(float4*)(sY + o);                                         \
                float4 a = *(float4*)(sK1 + o);                                        \
                float4 b = *(float4*)(sK2 + o);                                        \
                *(float4*)(sAR + o) = make_float4(y.x + dt_ * (b.x - th * a.x),        \
                                                  y.y + dt_ * (b.y - th * a.y),        \
                                                  y.z + dt_ * (b.z - th * a.z),        \
                                                  y.w + dt_ * (b.w - th * a.w));       \
            }                                                                          \
        }                                                                              \
        __syncthreads();                                                               \
        /* k3 = f(arg) */                                                              \
        gemm1(sAR, sW1, sb1, sHT, t); __syncthreads();                                 \
        gemm2(sK3, sHT, sW2, sb2, t); __syncthreads();                                 \
        { /* arg = y + dt*(k1 - k2 + k3) */                                            \
            _Pragma("unroll")                                                          \
            for (int i = 0; i < 16; i += 4) {                                          \
                int o = ew0 + i;                                                       \
                float4 y = *(float4*)(sY + o);                                         \
                float4 a = *(float4*)(sK1 + o);                                        \
                float4 b = *(float4*)(sK2 + o);                                        \
                float4 cc = *(float4*)(sK3 + o);                                       \
                *(float4*)(sAR + o) = make_float4(y.x + dt_ * (a.x - b.x + cc.x),      \
                                                  y.y + dt_ * (a.y - b.y + cc.y),      \
                                                  y.z + dt_ * (a.z - b.z + cc.z),      \
                                                  y.w + dt_ * (a.w - b.w + cc.w));     \
            }                                                                          \
        }                                                                              \
        __syncthreads();                                                               \
        /* k4 = f(arg) -> stored in sAR (gemm1 consumes sAR before gemm2 writes it) */ \
        gemm1(sAR, sW1, sb1, sHT, t); __syncthreads();                                 \
        gemm2(sAR, sHT, sW2, sb2, t); __syncthreads();                                 \
        { /* y += dt/8 * (k1 + 3*(k2+k3) + k4) */                                      \
            float c8 = dt_ * 0.125f;                                                   \
            _Pragma("unroll")                                                          \
            for (int i = 0; i < 16; i += 4) {                                          \
                int o = ew0 + i;                                                       \
                float4 y = *(float4*)(sY + o);                                         \
                float4 a = *(float4*)(sK1 + o);                                        \
                float4 b = *(float4*)(sK2 + o);                                        \
                float4 cc = *(float4*)(sK3 + o);                                       \
                float4 d = *(float4*)(sAR + o);                                        \
                *(float4*)(sY + o) = make_float4(                                      \
                    y.x + c8 * (a.x + 3.0f * (b.x + cc.x) + d.x),                      \
                    y.y + c8 * (a.y + 3.0f * (b.y + cc.y) + d.y),                      \
                    y.z + c8 * (a.z + 3.0f * (b.z + cc.z) + d.z),                      \
                    y.w + c8 * (a.w + 3.0f * (b.w + cc.w) + d.w));                     \
            }                                                                          \
        }                                                                              \
        __syncthreads();                                                               \
    }

    if (fw) {
        EMIT(idx);                       // j = idx is the initial state
        for (int s = idx; s < 95; s++) {
            float dt = sTs[s + 1] - sTs[s];
            RK4STEP(dt);
            EMIT(s + 1);
        }
    } else {
        for (int s = idx; s >= 1; s--) {
            float dt = sTs[s - 1] - sTs[s];   // negative
            RK4STEP(dt);
            EMIT(s - 1);
        }
    }
#undef RK4STEP
#undef EMIT
}

extern "C" void kernel_launch(void* const* d_in, const int* in_sizes, int n_in,
                              void* d_out, int out_size)
{
    const float* x  = (const float*)d_in[0];
    const float* ts = (const float*)d_in[1];
    const float* W1 = (const float*)d_in[2];
    const float* b1 = (const float*)d_in[3];
    const float* W2 = (const float*)d_in[4];
    const float* b2 = (const float*)d_in[5];
    float2* out = (float2*)d_out;

    const int smem_bytes = (8192 * 3 + 4096 * 5 + 128 + 64 + 96) * 4;  // 181376
    cudaFuncSetAttribute(ode_chain_kernel,
                         cudaFuncAttributeMaxDynamicSharedMemorySize, smem_bytes);
    ode_chain_kernel<<<192, NT, smem_bytes>>>(x, ts, W1, b1, W2, b2, out);
}